// round 6
// baseline (speedup 1.0000x reference)
#include <cuda_runtime.h>

#define NUM_GRAPHS 16384
#define C 128
#define C2 256

// Scratch (static device globals — no allocation in kernel_launch)
__device__ float         g_pooled[(size_t)NUM_GRAPHS * C];
__device__ unsigned char g_nonempty[NUM_GRAPHS];

// ---------------------------------------------------------------------------
// Kernel 1: fused segment lookup + gate + online segment-softmax + pooling.
// One warp per graph, lane = 4 channels (float4).
//   - lanes 0/1 binary-search sorted batch for offsets of g / g+1 (broadcast)
//   - 4 rows per group, explicit prefetch of next group (8 LDG.128 in flight)
//   - merged 4-sum warp reduction: 10 SHFL per group
// Dtype-robust: JAX x64-disabled stores "int64" as int32; probe an odd 32-bit
// word (int64 high word == 0, int32 late id > 0).
// ---------------------------------------------------------------------------
__global__ __launch_bounds__(256) void pool_kernel(
    const float4* __restrict__ x4,        // [N, 32] float4 view of [N,128]
    const int*    __restrict__ batch32,   // [N] (or [N] int64 viewed as int32)
    int n,
    const float4* __restrict__ gate_w4,   // [32] float4 view of [128]
    const float*  __restrict__ gate_b)    // [1]
{
    const int warp = threadIdx.x >> 5;
    const int lane = threadIdx.x & 31;
    const int g = blockIdx.x * 8 + warp;

    // --- segment offsets via in-warp binary search ---
    int probe_idx = ((n - 1) & 1) ? (n - 1) : (n - 2);   // odd index < n
    bool is_i32 = (probe_idx >= 1) && (__ldg(&batch32[probe_idx]) != 0);

    int target = g + (lane & 1);   // even lanes search g, odd lanes g+1
    int blo = 0, bhi = n;
    if (is_i32) {
        while (blo < bhi) {
            int mid = (blo + bhi) >> 1;
            if (__ldg(&batch32[mid]) < target) blo = mid + 1; else bhi = mid;
        }
    } else {
        while (blo < bhi) {
            int mid = (blo + bhi) >> 1;
            if (__ldg(&batch32[2 * mid]) < target) blo = mid + 1; else bhi = mid;
        }
    }
    const int lo = __shfl_sync(0xffffffffu, blo, 0);
    const int hi = __shfl_sync(0xffffffffu, blo, 1);

    float4* pooled_out = reinterpret_cast<float4*>(g_pooled) + (size_t)g * 32 + lane;

    if (lane == 0) g_nonempty[g] = (lo < hi) ? 1 : 0;
    if (lo >= hi) {
        *pooled_out = make_float4(0.f, 0.f, 0.f, 0.f);
        return;
    }

    const float4 gw = gate_w4[lane];
    const float  gb = gate_b[0];

    float  m = -INFINITY;
    float  s = 0.0f;
    float4 acc = make_float4(0.f, 0.f, 0.f, 0.f);

    const int last = hi - 1;

    // initial group load (clamped)
    float4 v0 = x4[(size_t)lo * 32 + lane];
    float4 v1 = x4[(size_t)min(lo + 1, last) * 32 + lane];
    float4 v2 = x4[(size_t)min(lo + 2, last) * 32 + lane];
    float4 v3 = x4[(size_t)min(lo + 3, last) * 32 + lane];

    for (int r = lo; r < hi; r += 4) {
        // prefetch next group (clamped; last-iter redundant loads are L1 hits)
        int rn = r + 4;
        float4 n0 = x4[(size_t)min(rn + 0, last) * 32 + lane];
        float4 n1 = x4[(size_t)min(rn + 1, last) * 32 + lane];
        float4 n2 = x4[(size_t)min(rn + 2, last) * 32 + lane];
        float4 n3 = x4[(size_t)min(rn + 3, last) * 32 + lane];

        // per-lane gate partials (4 independent rows)
        float p0 = v0.x*gw.x + v0.y*gw.y + v0.z*gw.z + v0.w*gw.w;
        float p1 = v1.x*gw.x + v1.y*gw.y + v1.z*gw.z + v1.w*gw.w;
        float p2 = v2.x*gw.x + v2.y*gw.y + v2.z*gw.z + v2.w*gw.w;
        float p3 = v3.x*gw.x + v3.y*gw.y + v3.z*gw.z + v3.w*gw.w;

        // merged 4-sum warp reduction (10 SHFL total)
        float ua = (lane & 1) ? p1 : p0;
        float ub = (lane & 1) ? p0 : p1;
        ua += __shfl_xor_sync(0xffffffffu, ub, 1);
        float va = (lane & 1) ? p3 : p2;
        float vb = (lane & 1) ? p2 : p3;
        va += __shfl_xor_sync(0xffffffffu, vb, 1);
        float wa = (lane & 2) ? va : ua;
        float wb = (lane & 2) ? ua : va;
        wa += __shfl_xor_sync(0xffffffffu, wb, 2);
        wa += __shfl_xor_sync(0xffffffffu, wa, 4);
        wa += __shfl_xor_sync(0xffffffffu, wa, 8);
        wa += __shfl_xor_sync(0xffffffffu, wa, 16);
        // lane j (j=0..3) now holds S_j; broadcast all four
        float s0 = __shfl_sync(0xffffffffu, wa, 0) + gb;
        float s1 = __shfl_sync(0xffffffffu, wa, 1) + gb;
        float s2 = __shfl_sync(0xffffffffu, wa, 2) + gb;
        float s3 = __shfl_sync(0xffffffffu, wa, 3) + gb;

        // mask padded rows
        if (r + 1 >= hi) s1 = -INFINITY;
        if (r + 2 >= hi) s2 = -INFINITY;
        if (r + 3 >= hi) s3 = -INFINITY;

        float mg    = fmaxf(fmaxf(s0, s1), fmaxf(s2, s3));
        float m_new = fmaxf(m, mg);
        float alpha = __expf(m - m_new);          // exp(-inf)=0 on first group
        float e0 = __expf(s0 - m_new);
        float e1 = __expf(s1 - m_new);
        float e2 = __expf(s2 - m_new);
        float e3 = __expf(s3 - m_new);

        s = fmaf(s, alpha, (e0 + e1) + (e2 + e3));
        acc.x = fmaf(acc.x, alpha, fmaf(e1, v1.x, e0 * v0.x) + fmaf(e3, v3.x, e2 * v2.x));
        acc.y = fmaf(acc.y, alpha, fmaf(e1, v1.y, e0 * v0.y) + fmaf(e3, v3.y, e2 * v2.y));
        acc.z = fmaf(acc.z, alpha, fmaf(e1, v1.z, e0 * v0.z) + fmaf(e3, v3.z, e2 * v2.z));
        acc.w = fmaf(acc.w, alpha, fmaf(e1, v1.w, e0 * v0.w) + fmaf(e3, v3.w, e2 * v2.w));
        m = m_new;

        v0 = n0; v1 = n1; v2 = n2; v3 = n3;
    }

    float inv = __frcp_rn(s);
    float4 outv;
    outv.x = acc.x * inv;
    outv.y = acc.y * inv;
    outv.z = acc.z * inv;
    outv.w = acc.w * inv;
    *pooled_out = outv;
}

// ---------------------------------------------------------------------------
// Kernel 2: out = pooled @ nn_w + nn_b (empty-graph zeroing), using packed
// fp32x2 FMA (sm_103a). Two k-partials per accumulator; ps pairs read as the
// 64-bit lanes of an LDS.128.
// ---------------------------------------------------------------------------
__device__ __forceinline__ void fma_f32x2(unsigned long long& d,
                                          unsigned long long a,
                                          unsigned long long b,
                                          unsigned long long c) {
    asm("fma.rn.f32x2 %0, %1, %2, %3;" : "=l"(d) : "l"(a), "l"(b), "l"(c));
}

__global__ __launch_bounds__(256) void gemm_kernel(
    const float* __restrict__ nn_w,   // [128, 256] row-major
    const float* __restrict__ nn_b,   // [256]
    float* __restrict__ out)          // [16384, 256]
{
    __shared__ float ps[16][C];       // pooled tile: 16 graphs x 128 ch = 8 KB

    const int t  = threadIdx.x;       // 0..255 -> output column j
    const int g0 = blockIdx.x * 16;

    // cooperative load of pooled tile (float4, coalesced)
    {
        const float4* src = reinterpret_cast<const float4*>(g_pooled + (size_t)g0 * C);
        float4* dst = reinterpret_cast<float4*>(&ps[0][0]);
        dst[t]       = src[t];
        dst[t + 256] = src[t + 256];
    }
    __syncthreads();

    const int j = t;
    unsigned long long acc2[16];
    #pragma unroll
    for (int g = 0; g < 16; ++g) acc2[g] = 0ull;

    #pragma unroll 1
    for (int k = 0; k < C; k += 4) {
        float w0 = nn_w[(k + 0) * C2 + j];
        float w1 = nn_w[(k + 1) * C2 + j];
        float w2 = nn_w[(k + 2) * C2 + j];
        float w3 = nn_w[(k + 3) * C2 + j];
        unsigned long long wp01, wp23;
        asm("mov.b64 %0, {%1, %2};" : "=l"(wp01) : "f"(w0), "f"(w1));
        asm("mov.b64 %0, {%1, %2};" : "=l"(wp23) : "f"(w2), "f"(w3));

        #pragma unroll
        for (int g = 0; g < 16; ++g) {
            ulonglong2 p = *reinterpret_cast<const ulonglong2*>(&ps[g][k]); // LDS.128
            fma_f32x2(acc2[g], p.x, wp01, acc2[g]);
            fma_f32x2(acc2[g], p.y, wp23, acc2[g]);
        }
    }

    const float b = nn_b[j];
    #pragma unroll
    for (int g = 0; g < 16; ++g) {
        float alo, ahi;
        asm("mov.b64 {%0, %1}, %2;" : "=f"(alo), "=f"(ahi) : "l"(acc2[g]));
        out[(size_t)(g0 + g) * C2 + j] = g_nonempty[g0 + g] ? (alo + ahi + b) : 0.0f;
    }
}

// ---------------------------------------------------------------------------
// kernel_launch
// Inputs (metadata order): x [N,128] f32, batch [N] (int32 on device), gate_w,
//                          gate_b, nn_w [128,256] f32, nn_b [256] f32
// Output: [16384, 256] f32
// ---------------------------------------------------------------------------
extern "C" void kernel_launch(void* const* d_in, const int* in_sizes, int n_in,
                              void* d_out, int out_size) {
    const float* x      = (const float*)d_in[0];
    const int*   batch  = (const int*)d_in[1];
    const float* gate_w = (const float*)d_in[2];
    const float* gate_b = (const float*)d_in[3];
    const float* nn_w   = (const float*)d_in[4];
    const float* nn_b   = (const float*)d_in[5];
    float*       out    = (float*)d_out;

    const int N = in_sizes[1];   // number of nodes

    pool_kernel<<<NUM_GRAPHS / 8, 256>>>(
        reinterpret_cast<const float4*>(x),
        batch, N,
        reinterpret_cast<const float4*>(gate_w),
        gate_b);
    gemm_kernel<<<NUM_GRAPHS / 16, 256>>>(nn_w, nn_b, out);
}

// round 7
// speedup vs baseline: 1.1052x; 1.1052x over previous
#include <cuda_runtime.h>

#define NUM_GRAPHS 16384
#define C 128
#define C2 256

// Scratch (static device globals — no allocation in kernel_launch)
__device__ int   g_offs[NUM_GRAPHS + 1];
__device__ float g_pooled[(size_t)NUM_GRAPHS * C];

// ---------------------------------------------------------------------------
// Kernel 0: segment offsets via vectorized coalesced boundary scan.
// Each thread handles 4 logical elements. g_offs[g] = first i with batch[i]>=g.
// Dtype-robust: JAX x64-disabled stores "int64" as int32; probe an odd 32-bit
// word (int64 high word == 0, int32 late id > 0).
// ---------------------------------------------------------------------------
__global__ void seg_offsets_kernel(const int* __restrict__ batch32, int n) {
    int tid  = blockIdx.x * blockDim.x + threadIdx.x;
    int base = tid * 4;
    if (base >= n) return;

    int probe_idx = ((n - 1) & 1) ? (n - 1) : (n - 2);   // odd index < n
    bool is_i32 = (probe_idx >= 1) && (__ldg(&batch32[probe_idx]) != 0);

    int c[5];
    if (is_i32) {
        if (base + 4 <= n) {
            int4 q = *reinterpret_cast<const int4*>(batch32 + base);
            c[0] = q.x; c[1] = q.y; c[2] = q.z; c[3] = q.w;
        } else {
            #pragma unroll
            for (int k = 0; k < 4; ++k)
                c[k] = (base + k < n) ? batch32[base + k] : NUM_GRAPHS;
        }
        c[4] = (base + 4 < n) ? batch32[base + 4] : NUM_GRAPHS;
    } else {
        #pragma unroll
        for (int k = 0; k < 5; ++k)
            c[k] = (base + k < n) ? batch32[2 * (base + k)] : NUM_GRAPHS;
    }

    if (base == 0) {
        for (int g = 0; g <= c[0]; ++g) g_offs[g] = 0;
    }
    #pragma unroll
    for (int k = 0; k < 4; ++k) {
        int j = base + k;
        if (j >= n) break;
        for (int g = c[k] + 1; g <= c[k + 1]; ++g) g_offs[g] = j + 1;
    }
}

// ---------------------------------------------------------------------------
// Kernel 1: fused gate + online segment-softmax + weighted pooling.
// One warp per graph, lane = 4 channels (float4). 4 rows per group with
// explicit prefetch of the next group; merged 4-sum reduction (10 SHFL).
// ---------------------------------------------------------------------------
__global__ __launch_bounds__(256) void pool_kernel(
    const float4* __restrict__ x4,        // [N, 32] float4 view of [N,128]
    const float4* __restrict__ gate_w4,   // [32] float4 view of [128]
    const float*  __restrict__ gate_b)    // [1]
{
    const int warp = threadIdx.x >> 5;
    const int lane = threadIdx.x & 31;
    const int g = blockIdx.x * 8 + warp;

    const int lo = g_offs[g];
    const int hi = g_offs[g + 1];

    float4* pooled_out = reinterpret_cast<float4*>(g_pooled) + (size_t)g * 32 + lane;

    if (lo >= hi) {
        *pooled_out = make_float4(0.f, 0.f, 0.f, 0.f);
        return;
    }

    const float4 gw = gate_w4[lane];
    const float  gb = gate_b[0];

    float  m = -INFINITY;
    float  s = 0.0f;
    float4 acc = make_float4(0.f, 0.f, 0.f, 0.f);

    const int last = hi - 1;

    float4 v0 = x4[(size_t)lo * 32 + lane];
    float4 v1 = x4[(size_t)min(lo + 1, last) * 32 + lane];
    float4 v2 = x4[(size_t)min(lo + 2, last) * 32 + lane];
    float4 v3 = x4[(size_t)min(lo + 3, last) * 32 + lane];

    for (int r = lo; r < hi; r += 4) {
        int rn = r + 4;
        float4 n0 = x4[(size_t)min(rn + 0, last) * 32 + lane];
        float4 n1 = x4[(size_t)min(rn + 1, last) * 32 + lane];
        float4 n2 = x4[(size_t)min(rn + 2, last) * 32 + lane];
        float4 n3 = x4[(size_t)min(rn + 3, last) * 32 + lane];

        float p0 = v0.x*gw.x + v0.y*gw.y + v0.z*gw.z + v0.w*gw.w;
        float p1 = v1.x*gw.x + v1.y*gw.y + v1.z*gw.z + v1.w*gw.w;
        float p2 = v2.x*gw.x + v2.y*gw.y + v2.z*gw.z + v2.w*gw.w;
        float p3 = v3.x*gw.x + v3.y*gw.y + v3.z*gw.z + v3.w*gw.w;

        // merged 4-sum warp reduction (10 SHFL total)
        float ua = (lane & 1) ? p1 : p0;
        float ub = (lane & 1) ? p0 : p1;
        ua += __shfl_xor_sync(0xffffffffu, ub, 1);
        float va = (lane & 1) ? p3 : p2;
        float vb = (lane & 1) ? p2 : p3;
        va += __shfl_xor_sync(0xffffffffu, vb, 1);
        float wa = (lane & 2) ? va : ua;
        float wb = (lane & 2) ? ua : va;
        wa += __shfl_xor_sync(0xffffffffu, wb, 2);
        wa += __shfl_xor_sync(0xffffffffu, wa, 4);
        wa += __shfl_xor_sync(0xffffffffu, wa, 8);
        wa += __shfl_xor_sync(0xffffffffu, wa, 16);
        float s0 = __shfl_sync(0xffffffffu, wa, 0) + gb;
        float s1 = __shfl_sync(0xffffffffu, wa, 1) + gb;
        float s2 = __shfl_sync(0xffffffffu, wa, 2) + gb;
        float s3 = __shfl_sync(0xffffffffu, wa, 3) + gb;

        if (r + 1 >= hi) s1 = -INFINITY;
        if (r + 2 >= hi) s2 = -INFINITY;
        if (r + 3 >= hi) s3 = -INFINITY;

        float mg    = fmaxf(fmaxf(s0, s1), fmaxf(s2, s3));
        float m_new = fmaxf(m, mg);
        float alpha = __expf(m - m_new);
        float e0 = __expf(s0 - m_new);
        float e1 = __expf(s1 - m_new);
        float e2 = __expf(s2 - m_new);
        float e3 = __expf(s3 - m_new);

        s = fmaf(s, alpha, (e0 + e1) + (e2 + e3));
        acc.x = fmaf(acc.x, alpha, fmaf(e1, v1.x, e0 * v0.x) + fmaf(e3, v3.x, e2 * v2.x));
        acc.y = fmaf(acc.y, alpha, fmaf(e1, v1.y, e0 * v0.y) + fmaf(e3, v3.y, e2 * v2.y));
        acc.z = fmaf(acc.z, alpha, fmaf(e1, v1.z, e0 * v0.z) + fmaf(e3, v3.z, e2 * v2.z));
        acc.w = fmaf(acc.w, alpha, fmaf(e1, v1.w, e0 * v0.w) + fmaf(e3, v3.w, e2 * v2.w));
        m = m_new;

        v0 = n0; v1 = n1; v2 = n2; v3 = n3;
    }

    float inv = __frcp_rn(s);
    float4 outv;
    outv.x = acc.x * inv;
    outv.y = acc.y * inv;
    outv.z = acc.z * inv;
    outv.w = acc.w * inv;
    *pooled_out = outv;
}

// ---------------------------------------------------------------------------
// Kernel 2: out = pooled @ nn_w + nn_b, register-tiled.
// Block = 128 threads covering 16 graphs x 256 cols. Thread microtile:
// 8 graphs x 4 cols (jt = t & 63 -> cols 4*jt.., gt = t >> 6 -> graphs 8*gt..).
// Per 4-k step: 8 LDS.128 (broadcast) + 4 LDG.128 (W, coalesced/L1) +
// 8 packs + 32 fp32x2 FMAs. 8x less LDS traffic than 1-col version.
// ---------------------------------------------------------------------------
__device__ __forceinline__ void fma_f32x2(unsigned long long& d,
                                          unsigned long long a,
                                          unsigned long long b,
                                          unsigned long long c) {
    asm("fma.rn.f32x2 %0, %1, %2, %3;" : "=l"(d) : "l"(a), "l"(b), "l"(c));
}
__device__ __forceinline__ unsigned long long pack2(float lo, float hi) {
    unsigned long long r;
    asm("mov.b64 %0, {%1, %2};" : "=l"(r) : "f"(lo), "f"(hi));
    return r;
}

__global__ __launch_bounds__(128) void gemm_kernel(
    const float* __restrict__ nn_w,   // [128, 256] row-major
    const float* __restrict__ nn_b,   // [256]
    float* __restrict__ out)          // [16384, 256]
{
    __shared__ float ps[16][C];       // pooled tile: 16 graphs x 128 ch = 8 KB

    const int t  = threadIdx.x;       // 128 threads
    const int g0 = blockIdx.x * 16;
    const int jt = t & 63;            // 64 col-groups
    const int gt = t >> 6;            // 2 graph-groups
    const int c0 = jt * 4;
    const int gb = gt * 8;

    // cooperative load of pooled tile (float4, coalesced): 512 float4 / 128 thr
    {
        const float4* src = reinterpret_cast<const float4*>(g_pooled + (size_t)g0 * C);
        float4* dst = reinterpret_cast<float4*>(&ps[0][0]);
        #pragma unroll
        for (int i = 0; i < 4; ++i) dst[t + i * 128] = src[t + i * 128];
    }
    __syncthreads();

    unsigned long long acc2[8][4];
    #pragma unroll
    for (int g = 0; g < 8; ++g)
        #pragma unroll
        for (int c = 0; c < 4; ++c) acc2[g][c] = 0ull;

    #pragma unroll 1
    for (int k = 0; k < C; k += 4) {
        float4 w0 = *reinterpret_cast<const float4*>(&nn_w[(k + 0) * C2 + c0]);
        float4 w1 = *reinterpret_cast<const float4*>(&nn_w[(k + 1) * C2 + c0]);
        float4 w2 = *reinterpret_cast<const float4*>(&nn_w[(k + 2) * C2 + c0]);
        float4 w3 = *reinterpret_cast<const float4*>(&nn_w[(k + 3) * C2 + c0]);

        unsigned long long wp01[4], wp23[4];
        wp01[0] = pack2(w0.x, w1.x); wp23[0] = pack2(w2.x, w3.x);
        wp01[1] = pack2(w0.y, w1.y); wp23[1] = pack2(w2.y, w3.y);
        wp01[2] = pack2(w0.z, w1.z); wp23[2] = pack2(w2.z, w3.z);
        wp01[3] = pack2(w0.w, w1.w); wp23[3] = pack2(w2.w, w3.w);

        #pragma unroll
        for (int g = 0; g < 8; ++g) {
            ulonglong2 p = *reinterpret_cast<const ulonglong2*>(&ps[gb + g][k]); // LDS.128
            #pragma unroll
            for (int c = 0; c < 4; ++c) {
                fma_f32x2(acc2[g][c], p.x, wp01[c], acc2[g][c]);
                fma_f32x2(acc2[g][c], p.y, wp23[c], acc2[g][c]);
            }
        }
    }

    const float4 bias = *reinterpret_cast<const float4*>(&nn_b[c0]);
    #pragma unroll
    for (int g = 0; g < 8; ++g) {
        int gg = g0 + gb + g;
        bool nonempty = g_offs[gg + 1] > g_offs[gg];
        float4 o;
        float lo, hi;
        asm("mov.b64 {%0, %1}, %2;" : "=f"(lo), "=f"(hi) : "l"(acc2[g][0]));
        o.x = lo + hi + bias.x;
        asm("mov.b64 {%0, %1}, %2;" : "=f"(lo), "=f"(hi) : "l"(acc2[g][1]));
        o.y = lo + hi + bias.y;
        asm("mov.b64 {%0, %1}, %2;" : "=f"(lo), "=f"(hi) : "l"(acc2[g][2]));
        o.z = lo + hi + bias.z;
        asm("mov.b64 {%0, %1}, %2;" : "=f"(lo), "=f"(hi) : "l"(acc2[g][3]));
        o.w = lo + hi + bias.w;
        if (!nonempty) o = make_float4(0.f, 0.f, 0.f, 0.f);
        *reinterpret_cast<float4*>(&out[(size_t)gg * C2 + c0]) = o;
    }
}

// ---------------------------------------------------------------------------
// kernel_launch
// Inputs (metadata order): x [N,128] f32, batch [N] (int32 on device), gate_w,
//                          gate_b, nn_w [128,256] f32, nn_b [256] f32
// Output: [16384, 256] f32
// ---------------------------------------------------------------------------
extern "C" void kernel_launch(void* const* d_in, const int* in_sizes, int n_in,
                              void* d_out, int out_size) {
    const float* x      = (const float*)d_in[0];
    const int*   batch  = (const int*)d_in[1];
    const float* gate_w = (const float*)d_in[2];
    const float* gate_b = (const float*)d_in[3];
    const float* nn_w   = (const float*)d_in[4];
    const float* nn_b   = (const float*)d_in[5];
    float*       out    = (float*)d_out;

    const int N = in_sizes[1];   // number of nodes

    int seg_threads = (N + 3) / 4;
    seg_offsets_kernel<<<(seg_threads + 255) / 256, 256>>>(batch, N);
    pool_kernel<<<NUM_GRAPHS / 8, 256>>>(
        reinterpret_cast<const float4*>(x),
        reinterpret_cast<const float4*>(gate_w),
        gate_b);
    gemm_kernel<<<NUM_GRAPHS / 16, 128>>>(nn_w, nn_b, out);
}

// round 8
// speedup vs baseline: 1.1644x; 1.0536x over previous
#include <cuda_runtime.h>

#define NUM_GRAPHS 16384
#define C 128
#define C2 256

// Scratch (static device globals — no allocation in kernel_launch)
__device__ int           g_offs[NUM_GRAPHS + 1];
__device__ float         g_pooled[(size_t)NUM_GRAPHS * C];
__device__ ulonglong2    g_wq[64 * 2 * 64];   // packed W: [k2][h][cg], 128 KB

// ---------------------------------------------------------------------------
// Kernel 0: (a) segment offsets via vectorized boundary scan  (blocks < segB)
//           (b) W pre-pack into f32x2-pair layout             (blocks >= segB)
// Layout (b): wq[(k2*2+h)*64 + cg] = ( pack(W[2k2][c],W[2k2+1][c]),
//                                      pack(W[2k2][c+1],W[2k2+1][c+1]) ),
//             c = cg*4 + 2h. One ulonglong2 per thread, 8192 threads.
// Dtype-robust: JAX x64-disabled stores "int64" as int32; probe an odd 32-bit
// word (int64 high word == 0, int32 late id > 0).
// ---------------------------------------------------------------------------
__device__ __forceinline__ unsigned long long pack2(float lo, float hi) {
    unsigned long long r;
    asm("mov.b64 %0, {%1, %2};" : "=l"(r) : "f"(lo), "f"(hi));
    return r;
}

__global__ void seg_pack_kernel(const int* __restrict__ batch32, int n,
                                int segBlocks, const float* __restrict__ nn_w) {
    if ((int)blockIdx.x >= segBlocks) {
        // ---- W pre-pack ----
        int p = (blockIdx.x - segBlocks) * 256 + threadIdx.x;   // 0..8191
        int k2  = p >> 7;
        int rem = p & 127;
        int h   = rem >> 6;
        int cg  = rem & 63;
        int c   = cg * 4 + 2 * h;
        float a0 = nn_w[(2 * k2)     * C2 + c];
        float a1 = nn_w[(2 * k2 + 1) * C2 + c];
        float b0 = nn_w[(2 * k2)     * C2 + c + 1];
        float b1 = nn_w[(2 * k2 + 1) * C2 + c + 1];
        ulonglong2 v;
        v.x = pack2(a0, a1);
        v.y = pack2(b0, b1);
        g_wq[p] = v;
        return;
    }

    // ---- segment offsets ----
    int tid  = blockIdx.x * blockDim.x + threadIdx.x;
    int base = tid * 4;
    if (base >= n) return;

    int probe_idx = ((n - 1) & 1) ? (n - 1) : (n - 2);   // odd index < n
    bool is_i32 = (probe_idx >= 1) && (__ldg(&batch32[probe_idx]) != 0);

    int c[5];
    if (is_i32) {
        if (base + 4 <= n) {
            int4 q = *reinterpret_cast<const int4*>(batch32 + base);
            c[0] = q.x; c[1] = q.y; c[2] = q.z; c[3] = q.w;
        } else {
            #pragma unroll
            for (int k = 0; k < 4; ++k)
                c[k] = (base + k < n) ? batch32[base + k] : NUM_GRAPHS;
        }
        c[4] = (base + 4 < n) ? batch32[base + 4] : NUM_GRAPHS;
    } else {
        #pragma unroll
        for (int k = 0; k < 5; ++k)
            c[k] = (base + k < n) ? batch32[2 * (base + k)] : NUM_GRAPHS;
    }

    if (base == 0) {
        for (int g = 0; g <= c[0]; ++g) g_offs[g] = 0;
    }
    #pragma unroll
    for (int k = 0; k < 4; ++k) {
        int j = base + k;
        if (j >= n) break;
        for (int g = c[k] + 1; g <= c[k + 1]; ++g) g_offs[g] = j + 1;
    }
}

// ---------------------------------------------------------------------------
// Kernel 1: fused gate + online segment-softmax + weighted pooling.
// One warp per graph, lane = 4 channels (float4). 4 rows per group with
// explicit prefetch of the next group; merged 4-sum reduction (10 SHFL).
// ---------------------------------------------------------------------------
__global__ __launch_bounds__(256) void pool_kernel(
    const float4* __restrict__ x4,        // [N, 32] float4 view of [N,128]
    const float4* __restrict__ gate_w4,   // [32] float4 view of [128]
    const float*  __restrict__ gate_b)    // [1]
{
    const int warp = threadIdx.x >> 5;
    const int lane = threadIdx.x & 31;
    const int g = blockIdx.x * 8 + warp;

    const int lo = g_offs[g];
    const int hi = g_offs[g + 1];

    float4* pooled_out = reinterpret_cast<float4*>(g_pooled) + (size_t)g * 32 + lane;

    if (lo >= hi) {
        *pooled_out = make_float4(0.f, 0.f, 0.f, 0.f);
        return;
    }

    const float4 gw = gate_w4[lane];
    const float  gb = gate_b[0];

    float  m = -INFINITY;
    float  s = 0.0f;
    float4 acc = make_float4(0.f, 0.f, 0.f, 0.f);

    const int last = hi - 1;

    float4 v0 = x4[(size_t)lo * 32 + lane];
    float4 v1 = x4[(size_t)min(lo + 1, last) * 32 + lane];
    float4 v2 = x4[(size_t)min(lo + 2, last) * 32 + lane];
    float4 v3 = x4[(size_t)min(lo + 3, last) * 32 + lane];

    for (int r = lo; r < hi; r += 4) {
        int rn = r + 4;
        float4 n0 = x4[(size_t)min(rn + 0, last) * 32 + lane];
        float4 n1 = x4[(size_t)min(rn + 1, last) * 32 + lane];
        float4 n2 = x4[(size_t)min(rn + 2, last) * 32 + lane];
        float4 n3 = x4[(size_t)min(rn + 3, last) * 32 + lane];

        float p0 = v0.x*gw.x + v0.y*gw.y + v0.z*gw.z + v0.w*gw.w;
        float p1 = v1.x*gw.x + v1.y*gw.y + v1.z*gw.z + v1.w*gw.w;
        float p2 = v2.x*gw.x + v2.y*gw.y + v2.z*gw.z + v2.w*gw.w;
        float p3 = v3.x*gw.x + v3.y*gw.y + v3.z*gw.z + v3.w*gw.w;

        // merged 4-sum warp reduction (10 SHFL total)
        float ua = (lane & 1) ? p1 : p0;
        float ub = (lane & 1) ? p0 : p1;
        ua += __shfl_xor_sync(0xffffffffu, ub, 1);
        float va = (lane & 1) ? p3 : p2;
        float vb = (lane & 1) ? p2 : p3;
        va += __shfl_xor_sync(0xffffffffu, vb, 1);
        float wa = (lane & 2) ? va : ua;
        float wb = (lane & 2) ? ua : va;
        wa += __shfl_xor_sync(0xffffffffu, wb, 2);
        wa += __shfl_xor_sync(0xffffffffu, wa, 4);
        wa += __shfl_xor_sync(0xffffffffu, wa, 8);
        wa += __shfl_xor_sync(0xffffffffu, wa, 16);
        float s0 = __shfl_sync(0xffffffffu, wa, 0) + gb;
        float s1 = __shfl_sync(0xffffffffu, wa, 1) + gb;
        float s2 = __shfl_sync(0xffffffffu, wa, 2) + gb;
        float s3 = __shfl_sync(0xffffffffu, wa, 3) + gb;

        if (r + 1 >= hi) s1 = -INFINITY;
        if (r + 2 >= hi) s2 = -INFINITY;
        if (r + 3 >= hi) s3 = -INFINITY;

        float mg    = fmaxf(fmaxf(s0, s1), fmaxf(s2, s3));
        float m_new = fmaxf(m, mg);
        float alpha = __expf(m - m_new);
        float e0 = __expf(s0 - m_new);
        float e1 = __expf(s1 - m_new);
        float e2 = __expf(s2 - m_new);
        float e3 = __expf(s3 - m_new);

        s = fmaf(s, alpha, (e0 + e1) + (e2 + e3));
        acc.x = fmaf(acc.x, alpha, fmaf(e1, v1.x, e0 * v0.x) + fmaf(e3, v3.x, e2 * v2.x));
        acc.y = fmaf(acc.y, alpha, fmaf(e1, v1.y, e0 * v0.y) + fmaf(e3, v3.y, e2 * v2.y));
        acc.z = fmaf(acc.z, alpha, fmaf(e1, v1.z, e0 * v0.z) + fmaf(e3, v3.z, e2 * v2.z));
        acc.w = fmaf(acc.w, alpha, fmaf(e1, v1.w, e0 * v0.w) + fmaf(e3, v3.w, e2 * v2.w));
        m = m_new;

        v0 = n0; v1 = n1; v2 = n2; v3 = n3;
    }

    float inv = __frcp_rn(s);
    float4 outv;
    outv.x = acc.x * inv;
    outv.y = acc.y * inv;
    outv.z = acc.z * inv;
    outv.w = acc.w * inv;
    *pooled_out = outv;
}

// ---------------------------------------------------------------------------
// Kernel 2: out = pooled @ nn_w + nn_b, register-tiled, packed-W.
// 256 threads cover 32 graphs x 256 cols (grid 512). Microtile 8g x 4c.
// Hot loop per 4-k iter: 8 LDS.128 (uniform broadcast) + 4 LDG.128 (coalesced
// packed W) + 64 fp32x2 FMAs. No pack movs.
// ---------------------------------------------------------------------------
__device__ __forceinline__ void fma_f32x2(unsigned long long& d,
                                          unsigned long long a,
                                          unsigned long long b,
                                          unsigned long long c) {
    asm("fma.rn.f32x2 %0, %1, %2, %3;" : "=l"(d) : "l"(a), "l"(b), "l"(c));
}

__global__ __launch_bounds__(256) void gemm_kernel(
    const float* __restrict__ nn_b,   // [256]
    float* __restrict__ out)          // [16384, 256]
{
    __shared__ float ps[32][C];       // pooled tile: 32 graphs x 128 ch = 16 KB

    const int t  = threadIdx.x;       // 256 threads
    const int g0 = blockIdx.x * 32;
    const int cg = t & 63;            // 64 col-groups of 4
    const int gt = t >> 6;            // 4 graph-groups of 8
    const int c0 = cg * 4;
    const int gb = gt * 8;

    // cooperative load of pooled tile: 1024 float4 / 256 thr = 4 each
    {
        const float4* src = reinterpret_cast<const float4*>(g_pooled + (size_t)g0 * C);
        float4* dst = reinterpret_cast<float4*>(&ps[0][0]);
        #pragma unroll
        for (int i = 0; i < 4; ++i) dst[t + i * 256] = src[t + i * 256];
    }
    __syncthreads();

    unsigned long long acc2[8][4];
    #pragma unroll
    for (int g = 0; g < 8; ++g)
        #pragma unroll
        for (int c = 0; c < 4; ++c) acc2[g][c] = 0ull;

    #pragma unroll 1
    for (int i = 0; i < 32; ++i) {            // k = 4*i, k2 = 2*i
        // packed W: wA/wB for k2=2i (cols c0..c0+1 / c0+2..c0+3),
        //           wC/wD for k2=2i+1
        ulonglong2 wA = g_wq[((2 * i)     * 2 + 0) * 64 + cg];
        ulonglong2 wB = g_wq[((2 * i)     * 2 + 1) * 64 + cg];
        ulonglong2 wC = g_wq[((2 * i + 1) * 2 + 0) * 64 + cg];
        ulonglong2 wD = g_wq[((2 * i + 1) * 2 + 1) * 64 + cg];

        #pragma unroll
        for (int g = 0; g < 8; ++g) {
            ulonglong2 p = *reinterpret_cast<const ulonglong2*>(&ps[gb + g][4 * i]);
            // p.x = (pool[k], pool[k+1]) ; p.y = (pool[k+2], pool[k+3])
            fma_f32x2(acc2[g][0], p.x, wA.x, acc2[g][0]);
            fma_f32x2(acc2[g][1], p.x, wA.y, acc2[g][1]);
            fma_f32x2(acc2[g][2], p.x, wB.x, acc2[g][2]);
            fma_f32x2(acc2[g][3], p.x, wB.y, acc2[g][3]);
            fma_f32x2(acc2[g][0], p.y, wC.x, acc2[g][0]);
            fma_f32x2(acc2[g][1], p.y, wC.y, acc2[g][1]);
            fma_f32x2(acc2[g][2], p.y, wD.x, acc2[g][2]);
            fma_f32x2(acc2[g][3], p.y, wD.y, acc2[g][3]);
        }
    }

    const float4 bias = *reinterpret_cast<const float4*>(&nn_b[c0]);
    #pragma unroll
    for (int g = 0; g < 8; ++g) {
        int gg = g0 + gb + g;
        bool nonempty = g_offs[gg + 1] > g_offs[gg];
        float4 o;
        float lo, hi;
        asm("mov.b64 {%0, %1}, %2;" : "=f"(lo), "=f"(hi) : "l"(acc2[g][0]));
        o.x = lo + hi + bias.x;
        asm("mov.b64 {%0, %1}, %2;" : "=f"(lo), "=f"(hi) : "l"(acc2[g][1]));
        o.y = lo + hi + bias.y;
        asm("mov.b64 {%0, %1}, %2;" : "=f"(lo), "=f"(hi) : "l"(acc2[g][2]));
        o.z = lo + hi + bias.z;
        asm("mov.b64 {%0, %1}, %2;" : "=f"(lo), "=f"(hi) : "l"(acc2[g][3]));
        o.w = lo + hi + bias.w;
        if (!nonempty) o = make_float4(0.f, 0.f, 0.f, 0.f);
        *reinterpret_cast<float4*>(&out[(size_t)gg * C2 + c0]) = o;
    }
}

// ---------------------------------------------------------------------------
// kernel_launch
// Inputs (metadata order): x [N,128] f32, batch [N] (int32 on device), gate_w,
//                          gate_b, nn_w [128,256] f32, nn_b [256] f32
// Output: [16384, 256] f32
// ---------------------------------------------------------------------------
extern "C" void kernel_launch(void* const* d_in, const int* in_sizes, int n_in,
                              void* d_out, int out_size) {
    const float* x      = (const float*)d_in[0];
    const int*   batch  = (const int*)d_in[1];
    const float* gate_w = (const float*)d_in[2];
    const float* gate_b = (const float*)d_in[3];
    const float* nn_w   = (const float*)d_in[4];
    const float* nn_b   = (const float*)d_in[5];
    float*       out    = (float*)d_out;

    const int N = in_sizes[1];   // number of nodes

    int segBlocks  = ((N + 3) / 4 + 255) / 256;
    int packBlocks = 32;   // 8192 threads packing W
    seg_pack_kernel<<<segBlocks + packBlocks, 256>>>(batch, N, segBlocks, nn_w);
    pool_kernel<<<NUM_GRAPHS / 8, 256>>>(
        reinterpret_cast<const float4*>(x),
        reinterpret_cast<const float4*>(gate_w),
        gate_b);
    gemm_kernel<<<NUM_GRAPHS / 32, 256>>>(nn_b, out);
}